// round 1
// baseline (speedup 1.0000x reference)
#include <cuda_runtime.h>
#include <cuda_bf16.h>
#include <math.h>

#define MASK_SIZE 28
#define MASK_CELLS (MASK_SIZE * MASK_SIZE)   // 784
#define MAX_P 1024
#define IMG_H 520
#define IMG_W 704

// Scratch (device globals — no allocation allowed)
__device__ int   g_midx[MAX_P];
__device__ float g_pos[MAX_P];
__device__ float g_partial[MAX_P];

// ---------------------------------------------------------------------------
// Kernel 1: per-proposal max-IoU + argmax over G gt boxes.
// One block, P threads (P=512). gt boxes staged in shared.
// ---------------------------------------------------------------------------
__global__ void iou_argmax_kernel(const float* __restrict__ proposals,
                                  const float* __restrict__ gt_boxes,
                                  int P, int G)
{
    extern __shared__ float sb[];   // G*4 floats
    for (int i = threadIdx.x; i < G * 4; i += blockDim.x)
        sb[i] = gt_boxes[i];
    __syncthreads();

    int p = blockIdx.x * blockDim.x + threadIdx.x;
    if (p >= P) return;

    float ax1 = proposals[4 * p + 0];
    float ay1 = proposals[4 * p + 1];
    float ax2 = proposals[4 * p + 2];
    float ay2 = proposals[4 * p + 3];
    float area_a = (ax2 - ax1) * (ay2 - ay1);

    float best = -1.0f;
    int   bidx = 0;
    for (int g = 0; g < G; ++g) {
        float bx1 = sb[4 * g + 0];
        float by1 = sb[4 * g + 1];
        float bx2 = sb[4 * g + 2];
        float by2 = sb[4 * g + 3];
        float area_b = (bx2 - bx1) * (by2 - by1);
        float lx = fmaxf(ax1, bx1);
        float ly = fmaxf(ay1, by1);
        float rx = fminf(ax2, bx2);
        float ry = fminf(ay2, by2);
        float w = fmaxf(rx - lx, 0.0f);
        float h = fmaxf(ry - ly, 0.0f);
        float inter = w * h;
        float iou = inter / (area_a + area_b - inter);
        if (iou > best) { best = iou; bidx = g; }   // strict > == first-max (jnp.argmax)
    }
    g_midx[p] = bidx;
    g_pos[p]  = (best > 0.3f) ? 1.0f : 0.0f;
}

// ---------------------------------------------------------------------------
// Kernel 2: per proposal, bilinear target extraction + BCE, block-reduced
// partial sum -> g_partial[p]. Grid = P blocks, 256 threads.
// ---------------------------------------------------------------------------
__global__ void target_bce_kernel(const float* __restrict__ mask_logits,
                                  const float* __restrict__ gt_boxes,
                                  const float* __restrict__ gt_masks,
                                  int H, int W)
{
    int p = blockIdx.x;
    int tid = threadIdx.x;

    float posw = g_pos[p];
    if (posw == 0.0f) {
        if (tid == 0) g_partial[p] = 0.0f;
        return;
    }

    int g = g_midx[p];
    float b0 = gt_boxes[4 * g + 0];
    float b1 = gt_boxes[4 * g + 1];
    float b2 = gt_boxes[4 * g + 2];
    float b3 = gt_boxes[4 * g + 3];

    // truncation toward zero matches astype(int32) for non-negative coords
    int x1 = min(max((int)b0, 0), W - 1);
    int y1 = min(max((int)b1, 0), H - 1);
    int x2 = max(x1 + 1, min((int)b2, W));
    int y2 = max(y1 + 1, min((int)b3, H));
    float cw = (float)(x2 - x1);
    float ch = (float)(y2 - y1);
    int cwi = x2 - x1;
    int chi = y2 - y1;

    const float* m = gt_masks + (size_t)g * H * W;
    const float* lg = mask_logits + (size_t)p * 2 * MASK_CELLS + MASK_CELLS; // [:,1]

    float acc = 0.0f;
    for (int cell = tid; cell < MASK_CELLS; cell += blockDim.x) {
        int yj = cell / MASK_SIZE;
        int xi = cell - yj * MASK_SIZE;

        float sy = (yj + 0.5f) * ch * (1.0f / MASK_SIZE) - 0.5f;
        sy = fminf(fmaxf(sy, 0.0f), ch - 1.0f);
        float sx = (xi + 0.5f) * cw * (1.0f / MASK_SIZE) - 0.5f;
        sx = fminf(fmaxf(sx, 0.0f), cw - 1.0f);

        int y0 = (int)floorf(sy);
        int x0 = (int)floorf(sx);
        int yp = min(y0 + 1, chi - 1);
        int xp = min(x0 + 1, cwi - 1);
        float wy = sy - (float)y0;
        float wx = sx - (float)x0;

        int Y0 = y1 + y0, Y1 = y1 + yp;
        int X0 = x1 + x0, X1 = x1 + xp;

        float t00 = __ldg(&m[(size_t)Y0 * W + X0]);
        float t01 = __ldg(&m[(size_t)Y0 * W + X1]);
        float t10 = __ldg(&m[(size_t)Y1 * W + X0]);
        float t11 = __ldg(&m[(size_t)Y1 * W + X1]);

        float tgt = (1.0f - wy) * ((1.0f - wx) * t00 + wx * t01)
                  +          wy * ((1.0f - wx) * t10 + wx * t11);

        float l = lg[cell];
        // softplus(l) - l*tgt, stable form identical to jnp.logaddexp(l, 0)
        float bce = fmaxf(l, 0.0f) + log1pf(expf(-fabsf(l))) - l * tgt;
        acc += bce;
    }

    // deterministic block reduction (fixed tree order)
    __shared__ float red[256];
    red[tid] = acc;
    __syncthreads();
    for (int s = blockDim.x >> 1; s > 0; s >>= 1) {
        if (tid < s) red[tid] += red[tid + s];
        __syncthreads();
    }
    if (tid == 0) g_partial[p] = red[0];
}

// ---------------------------------------------------------------------------
// Kernel 3: finalize. One block of P threads; deterministic tree reduction.
// ---------------------------------------------------------------------------
__global__ void finalize_kernel(float* __restrict__ out, int P)
{
    __shared__ float rs[MAX_P];
    __shared__ float rp[MAX_P];
    int tid = threadIdx.x;
    float s = 0.0f, c = 0.0f;
    for (int i = tid; i < P; i += blockDim.x) {
        s += g_partial[i];
        c += g_pos[i];
    }
    rs[tid] = s;
    rp[tid] = c;
    __syncthreads();
    for (int st = blockDim.x >> 1; st > 0; st >>= 1) {
        if (tid < st) { rs[tid] += rs[tid + st]; rp[tid] += rp[tid + st]; }
        __syncthreads();
    }
    if (tid == 0) {
        float num_pos = rp[0];
        float denom = fmaxf(num_pos, 1.0f) * (float)(MASK_CELLS);
        out[0] = (num_pos > 0.0f) ? (rs[0] / denom) : 0.0f;
    }
}

// ---------------------------------------------------------------------------
// Inputs (metadata order):
//  0: mask_logits  float32  P*2*28*28
//  1: proposals    float32  P*4
//  2: gt_boxes     float32  G*4
//  3: gt_masks     float32  G*H*W
//  4: gt_labels    int32    G        (unused by the reference math)
// Output: scalar float32
// ---------------------------------------------------------------------------
extern "C" void kernel_launch(void* const* d_in, const int* in_sizes, int n_in,
                              void* d_out, int out_size)
{
    const float* mask_logits = (const float*)d_in[0];
    const float* proposals   = (const float*)d_in[1];
    const float* gt_boxes    = (const float*)d_in[2];
    const float* gt_masks    = (const float*)d_in[3];

    int P = in_sizes[1] / 4;
    int G = in_sizes[2] / 4;
    int HW = in_sizes[3] / G;
    int H = IMG_H, W = IMG_W;
    if (HW != IMG_H * IMG_W) { // fallback: assume square-ish not needed; keep fixed
        H = IMG_H; W = HW / IMG_H;
    }

    float* out = (float*)d_out;

    // K1: one block covers all proposals (P<=1024)
    iou_argmax_kernel<<<1, P, G * 4 * sizeof(float)>>>(proposals, gt_boxes, P, G);

    // K2: one block per proposal
    target_bce_kernel<<<P, 256>>>(mask_logits, gt_boxes, gt_masks, H, W);

    // K3: finalize
    finalize_kernel<<<1, P>>>(out, P);
}

// round 2
// speedup vs baseline: 3.5605x; 3.5605x over previous
#include <cuda_runtime.h>
#include <cuda_bf16.h>
#include <math.h>

#define MASK_SIZE 28
#define MASK_CELLS (MASK_SIZE * MASK_SIZE)   // 784
#define MAX_P 1024
#define IMG_H 520
#define IMG_W 704

// Scratch (device globals — no allocation allowed)
__device__ int   g_midx[MAX_P];
__device__ float g_pos[MAX_P];
__device__ float g_partial[MAX_P];

// ---------------------------------------------------------------------------
// Kernel 1: warp-per-proposal max-IoU + argmax over G gt boxes.
// 512 warps across the chip; each lane strides G, then shuffle-reduce.
// ---------------------------------------------------------------------------
__global__ void iou_argmax_kernel(const float* __restrict__ proposals,
                                  const float* __restrict__ gt_boxes,
                                  int P, int G)
{
    int gtid = blockIdx.x * blockDim.x + threadIdx.x;
    int p    = gtid >> 5;
    int lane = gtid & 31;
    if (p >= P) return;

    float4 a = __ldg((const float4*)proposals + p);
    float area_a = (a.z - a.x) * (a.w - a.y);

    float best = -1.0f;
    int   bidx = 0x7fffffff;
    for (int g = lane; g < G; g += 32) {
        float4 b = __ldg((const float4*)gt_boxes + g);
        float area_b = (b.z - b.x) * (b.w - b.y);
        float lx = fmaxf(a.x, b.x);
        float ly = fmaxf(a.y, b.y);
        float rx = fminf(a.z, b.z);
        float ry = fminf(a.w, b.w);
        float w = fmaxf(rx - lx, 0.0f);
        float h = fmaxf(ry - ly, 0.0f);
        float inter = w * h;
        float iou = inter / (area_a + area_b - inter);
        if (iou > best) { best = iou; bidx = g; }  // strict >: keeps lowest g in stride
    }
    // shuffle reduction: higher iou wins; exact tie -> lower index (first-max)
    #pragma unroll
    for (int off = 16; off > 0; off >>= 1) {
        float ob = __shfl_down_sync(0xffffffffu, best, off);
        int   oi = __shfl_down_sync(0xffffffffu, bidx, off);
        if (ob > best || (ob == best && oi < bidx)) { best = ob; bidx = oi; }
    }
    if (lane == 0) {
        g_midx[p] = bidx;
        g_pos[p]  = (best > 0.3f) ? 1.0f : 0.0f;
    }
}

// ---------------------------------------------------------------------------
// Kernel 2: per proposal, bilinear target extraction + BCE, block-reduced
// partial sum -> g_partial[p]. Grid = P blocks, 256 threads.
// ---------------------------------------------------------------------------
__global__ void target_bce_kernel(const float* __restrict__ mask_logits,
                                  const float* __restrict__ gt_boxes,
                                  const float* __restrict__ gt_masks,
                                  int H, int W)
{
    int p = blockIdx.x;
    int tid = threadIdx.x;

    float posw = g_pos[p];
    if (posw == 0.0f) {
        if (tid == 0) g_partial[p] = 0.0f;
        return;
    }

    int g = g_midx[p];
    float4 bb = __ldg((const float4*)gt_boxes + g);

    // truncation toward zero matches astype(int32) for non-negative coords
    int x1 = min(max((int)bb.x, 0), W - 1);
    int y1 = min(max((int)bb.y, 0), H - 1);
    int x2 = max(x1 + 1, min((int)bb.z, W));
    int y2 = max(y1 + 1, min((int)bb.w, H));
    float cw = (float)(x2 - x1);
    float ch = (float)(y2 - y1);
    int cwi = x2 - x1;
    int chi = y2 - y1;

    const float* m = gt_masks + (size_t)g * H * W;
    const float* lg = mask_logits + (size_t)p * 2 * MASK_CELLS + MASK_CELLS; // [:,1]

    float acc = 0.0f;
    for (int cell = tid; cell < MASK_CELLS; cell += blockDim.x) {
        int yj = cell / MASK_SIZE;
        int xi = cell - yj * MASK_SIZE;

        float sy = (yj + 0.5f) * ch * (1.0f / MASK_SIZE) - 0.5f;
        sy = fminf(fmaxf(sy, 0.0f), ch - 1.0f);
        float sx = (xi + 0.5f) * cw * (1.0f / MASK_SIZE) - 0.5f;
        sx = fminf(fmaxf(sx, 0.0f), cw - 1.0f);

        int y0 = (int)floorf(sy);
        int x0 = (int)floorf(sx);
        int yp = min(y0 + 1, chi - 1);
        int xp = min(x0 + 1, cwi - 1);
        float wy = sy - (float)y0;
        float wx = sx - (float)x0;

        int Y0 = y1 + y0, Y1 = y1 + yp;
        int X0 = x1 + x0, X1 = x1 + xp;

        float t00 = __ldg(&m[(size_t)Y0 * W + X0]);
        float t01 = __ldg(&m[(size_t)Y0 * W + X1]);
        float t10 = __ldg(&m[(size_t)Y1 * W + X0]);
        float t11 = __ldg(&m[(size_t)Y1 * W + X1]);

        float tgt = (1.0f - wy) * ((1.0f - wx) * t00 + wx * t01)
                  +          wy * ((1.0f - wx) * t10 + wx * t11);

        float l = lg[cell];
        // softplus(l) - l*tgt, stable form identical to jnp.logaddexp(l, 0)
        float bce = fmaxf(l, 0.0f) + log1pf(expf(-fabsf(l))) - l * tgt;
        acc += bce;
    }

    // deterministic block reduction (fixed tree order)
    __shared__ float red[256];
    red[tid] = acc;
    __syncthreads();
    for (int s = blockDim.x >> 1; s > 0; s >>= 1) {
        if (tid < s) red[tid] += red[tid + s];
        __syncthreads();
    }
    if (tid == 0) g_partial[p] = red[0];
}

// ---------------------------------------------------------------------------
// Kernel 3: finalize. One block of P threads; deterministic tree reduction.
// ---------------------------------------------------------------------------
__global__ void finalize_kernel(float* __restrict__ out, int P)
{
    __shared__ float rs[MAX_P];
    __shared__ float rp[MAX_P];
    int tid = threadIdx.x;
    float s = 0.0f, c = 0.0f;
    for (int i = tid; i < P; i += blockDim.x) {
        s += g_partial[i];
        c += g_pos[i];
    }
    rs[tid] = s;
    rp[tid] = c;
    __syncthreads();
    for (int st = blockDim.x >> 1; st > 0; st >>= 1) {
        if (tid < st) { rs[tid] += rs[tid + st]; rp[tid] += rp[tid + st]; }
        __syncthreads();
    }
    if (tid == 0) {
        float num_pos = rp[0];
        float denom = fmaxf(num_pos, 1.0f) * (float)(MASK_CELLS);
        out[0] = (num_pos > 0.0f) ? (rs[0] / denom) : 0.0f;
    }
}

// ---------------------------------------------------------------------------
// Inputs (metadata order):
//  0: mask_logits  float32  P*2*28*28
//  1: proposals    float32  P*4
//  2: gt_boxes     float32  G*4
//  3: gt_masks     float32  G*H*W
//  4: gt_labels    int32    G        (unused by the reference math)
// Output: scalar float32
// ---------------------------------------------------------------------------
extern "C" void kernel_launch(void* const* d_in, const int* in_sizes, int n_in,
                              void* d_out, int out_size)
{
    const float* mask_logits = (const float*)d_in[0];
    const float* proposals   = (const float*)d_in[1];
    const float* gt_boxes    = (const float*)d_in[2];
    const float* gt_masks    = (const float*)d_in[3];

    int P = in_sizes[1] / 4;
    int G = in_sizes[2] / 4;
    int HW = in_sizes[3] / G;
    int H = IMG_H, W = IMG_W;
    if (HW != IMG_H * IMG_W) {
        H = IMG_H; W = HW / IMG_H;
    }

    float* out = (float*)d_out;

    // K1: warp per proposal
    int threads1 = 256;
    int blocks1 = (P * 32 + threads1 - 1) / threads1;
    iou_argmax_kernel<<<blocks1, threads1>>>(proposals, gt_boxes, P, G);

    // K2: one block per proposal
    target_bce_kernel<<<P, 256>>>(mask_logits, gt_boxes, gt_masks, H, W);

    // K3: finalize
    finalize_kernel<<<1, P>>>(out, P);
}

// round 3
// speedup vs baseline: 4.1925x; 1.1775x over previous
#include <cuda_runtime.h>
#include <cuda_bf16.h>
#include <math.h>

#define MASK_SIZE 28
#define MASK_CELLS (MASK_SIZE * MASK_SIZE)   // 784
#define MAX_P 1024
#define NTHREADS 256

// Scratch (device globals — no allocation allowed)
__device__ float g_pos[MAX_P];
__device__ float g_partial[MAX_P];
__device__ unsigned int g_done = 0;

// ---------------------------------------------------------------------------
// Fused kernel: one block per proposal.
//  Stage A: block computes IoU row p (G gt boxes / 256 threads), argmax with
//           first-max tiebreak.
//  Stage B: bilinear target gather + BCE partial sum for this proposal.
//  Stage C: last block (threadfence + atomic counter) reduces all partials
//           deterministically and writes the scalar output.
// ---------------------------------------------------------------------------
__global__ void __launch_bounds__(NTHREADS)
fused_maskrcnn_kernel(const float* __restrict__ mask_logits,
                      const float* __restrict__ proposals,
                      const float* __restrict__ gt_boxes,
                      const float* __restrict__ gt_masks,
                      float* __restrict__ out,
                      int P, int G, int H, int W)
{
    int p = blockIdx.x;
    int tid = threadIdx.x;

    __shared__ float sbest[NTHREADS];
    __shared__ int   sidx[NTHREADS];
    __shared__ float red[NTHREADS];
    __shared__ float red2[NTHREADS];
    __shared__ int   s_is_last;

    // ---------------- Stage A: IoU row + argmax ----------------
    float4 a = __ldg((const float4*)proposals + p);
    float area_a = (a.z - a.x) * (a.w - a.y);

    float best = -1.0f;
    int   bidx = 0x7fffffff;
    for (int g = tid; g < G; g += NTHREADS) {
        float4 b = __ldg((const float4*)gt_boxes + g);
        float area_b = (b.z - b.x) * (b.w - b.y);
        float lx = fmaxf(a.x, b.x);
        float ly = fmaxf(a.y, b.y);
        float rx = fminf(a.z, b.z);
        float ry = fminf(a.w, b.w);
        float w = fmaxf(rx - lx, 0.0f);
        float h = fmaxf(ry - ly, 0.0f);
        float inter = w * h;
        float iou = inter / (area_a + area_b - inter);
        if (iou > best) { best = iou; bidx = g; }   // strict >: lowest g kept
    }
    sbest[tid] = best;
    sidx[tid]  = bidx;
    __syncthreads();
    for (int s = NTHREADS >> 1; s > 0; s >>= 1) {
        if (tid < s) {
            float ob = sbest[tid + s];
            int   oi = sidx[tid + s];
            if (ob > sbest[tid] || (ob == sbest[tid] && oi < sidx[tid])) {
                sbest[tid] = ob; sidx[tid] = oi;
            }
        }
        __syncthreads();
    }
    float maxiou = sbest[0];
    int   midx   = sidx[0];
    float posw   = (maxiou > 0.3f) ? 1.0f : 0.0f;

    // ---------------- Stage B: target gather + BCE ----------------
    float acc = 0.0f;
    if (posw != 0.0f) {
        float4 bb = __ldg((const float4*)gt_boxes + midx);
        // truncation toward zero matches astype(int32) for non-negative coords
        int x1 = min(max((int)bb.x, 0), W - 1);
        int y1 = min(max((int)bb.y, 0), H - 1);
        int x2 = max(x1 + 1, min((int)bb.z, W));
        int y2 = max(y1 + 1, min((int)bb.w, H));
        float cw = (float)(x2 - x1);
        float ch = (float)(y2 - y1);
        int cwi = x2 - x1;
        int chi = y2 - y1;

        const float* m  = gt_masks + (size_t)midx * H * W;
        const float* lg = mask_logits + (size_t)p * 2 * MASK_CELLS + MASK_CELLS;

        for (int cell = tid; cell < MASK_CELLS; cell += NTHREADS) {
            int yj = cell / MASK_SIZE;
            int xi = cell - yj * MASK_SIZE;

            float sy = (yj + 0.5f) * ch * (1.0f / MASK_SIZE) - 0.5f;
            sy = fminf(fmaxf(sy, 0.0f), ch - 1.0f);
            float sx = (xi + 0.5f) * cw * (1.0f / MASK_SIZE) - 0.5f;
            sx = fminf(fmaxf(sx, 0.0f), cw - 1.0f);

            int y0 = (int)floorf(sy);
            int x0 = (int)floorf(sx);
            int yp = min(y0 + 1, chi - 1);
            int xp = min(x0 + 1, cwi - 1);
            float wy = sy - (float)y0;
            float wx = sx - (float)x0;

            int Y0 = y1 + y0, Y1 = y1 + yp;
            int X0 = x1 + x0, X1 = x1 + xp;

            float t00 = __ldg(&m[(size_t)Y0 * W + X0]);
            float t01 = __ldg(&m[(size_t)Y0 * W + X1]);
            float t10 = __ldg(&m[(size_t)Y1 * W + X0]);
            float t11 = __ldg(&m[(size_t)Y1 * W + X1]);

            float tgt = (1.0f - wy) * ((1.0f - wx) * t00 + wx * t01)
                      +          wy * ((1.0f - wx) * t10 + wx * t11);

            float l = lg[cell];
            // softplus(l) - l*tgt, stable form identical to jnp.logaddexp(l, 0)
            float bce = fmaxf(l, 0.0f) + log1pf(expf(-fabsf(l))) - l * tgt;
            acc += bce;
        }
    }

    // deterministic block reduction
    red[tid] = acc;
    __syncthreads();
    for (int s = NTHREADS >> 1; s > 0; s >>= 1) {
        if (tid < s) red[tid] += red[tid + s];
        __syncthreads();
    }
    if (tid == 0) {
        g_partial[p] = red[0];
        g_pos[p]     = posw;
    }

    // ---------------- Stage C: last block finalizes ----------------
    if (tid == 0) {
        __threadfence();
        unsigned int prev = atomicAdd(&g_done, 1u);
        s_is_last = (prev == (unsigned int)(gridDim.x - 1)) ? 1 : 0;
    }
    __syncthreads();
    if (s_is_last) {
        float s = 0.0f, c = 0.0f;
        for (int i = tid; i < P; i += NTHREADS) {
            s += g_partial[i];
            c += g_pos[i];
        }
        red[tid]  = s;
        red2[tid] = c;
        __syncthreads();
        for (int st = NTHREADS >> 1; st > 0; st >>= 1) {
            if (tid < st) { red[tid] += red[tid + st]; red2[tid] += red2[tid + st]; }
            __syncthreads();
        }
        if (tid == 0) {
            float num_pos = red2[0];
            float denom = fmaxf(num_pos, 1.0f) * (float)MASK_CELLS;
            out[0] = (num_pos > 0.0f) ? (red[0] / denom) : 0.0f;
            g_done = 0;   // reset for next graph replay
        }
    }
}

// ---------------------------------------------------------------------------
// Inputs (metadata order):
//  0: mask_logits  float32  P*2*28*28
//  1: proposals    float32  P*4
//  2: gt_boxes     float32  G*4
//  3: gt_masks     float32  G*H*W
//  4: gt_labels    int32    G        (unused by the reference math)
// Output: scalar float32
// ---------------------------------------------------------------------------
extern "C" void kernel_launch(void* const* d_in, const int* in_sizes, int n_in,
                              void* d_out, int out_size)
{
    const float* mask_logits = (const float*)d_in[0];
    const float* proposals   = (const float*)d_in[1];
    const float* gt_boxes    = (const float*)d_in[2];
    const float* gt_masks    = (const float*)d_in[3];

    int P = in_sizes[1] / 4;
    int G = in_sizes[2] / 4;
    int HW = in_sizes[3] / G;
    int H = 520;
    int W = HW / H;

    float* out = (float*)d_out;

    fused_maskrcnn_kernel<<<P, NTHREADS>>>(mask_logits, proposals, gt_boxes,
                                           gt_masks, out, P, G, H, W);
}

// round 4
// speedup vs baseline: 4.8750x; 1.1628x over previous
#include <cuda_runtime.h>
#include <cuda_bf16.h>
#include <math.h>

#define MASK_SIZE 28
#define MASK_CELLS (MASK_SIZE * MASK_SIZE)   // 784
#define MAX_P 1024
#define NTHREADS 256
#define NWARPS (NTHREADS / 32)

// Scratch (device globals — no allocation allowed)
__device__ float g_pos[MAX_P];
__device__ float g_partial[MAX_P];
__device__ unsigned int g_done = 0;

// ---------------------------------------------------------------------------
// Fused kernel: one block per proposal.
//  A: IoU row p over G gt boxes, warp-shuffle argmax (first-max tiebreak)
//  B: bilinear target gather + BCE, fully unrolled for MLP, shuffle reduce
//  C: last block finalizes deterministically
// ---------------------------------------------------------------------------
__global__ void __launch_bounds__(NTHREADS)
fused_maskrcnn_kernel(const float* __restrict__ mask_logits,
                      const float* __restrict__ proposals,
                      const float* __restrict__ gt_boxes,
                      const float* __restrict__ gt_masks,
                      float* __restrict__ out,
                      int P, int G, int H, int W)
{
    int p    = blockIdx.x;
    int tid  = threadIdx.x;
    int lane = tid & 31;
    int wid  = tid >> 5;

    __shared__ float swb[NWARPS];
    __shared__ int   swi[NWARPS];
    __shared__ float sred[NWARPS];
    __shared__ float sred2[NWARPS];
    __shared__ float s_maxiou;
    __shared__ int   s_midx;
    __shared__ int   s_is_last;

    // ---------------- Stage A: IoU row + argmax ----------------
    float4 a = __ldg((const float4*)proposals + p);
    float area_a = (a.z - a.x) * (a.w - a.y);

    float best = -1.0f;
    int   bidx = 0x7fffffff;
    for (int g = tid; g < G; g += NTHREADS) {
        float4 b = __ldg((const float4*)gt_boxes + g);
        float area_b = (b.z - b.x) * (b.w - b.y);
        float lx = fmaxf(a.x, b.x);
        float ly = fmaxf(a.y, b.y);
        float rx = fminf(a.z, b.z);
        float ry = fminf(a.w, b.w);
        float w = fmaxf(rx - lx, 0.0f);
        float h = fmaxf(ry - ly, 0.0f);
        float inter = w * h;
        float iou = inter / (area_a + area_b - inter);
        if (iou > best) { best = iou; bidx = g; }   // strict >: lowest g kept
    }
    // warp argmax (first-max tiebreak: higher iou wins, tie -> lower index)
    #pragma unroll
    for (int off = 16; off > 0; off >>= 1) {
        float ob = __shfl_down_sync(0xffffffffu, best, off);
        int   oi = __shfl_down_sync(0xffffffffu, bidx, off);
        if (ob > best || (ob == best && oi < bidx)) { best = ob; bidx = oi; }
    }
    if (lane == 0) { swb[wid] = best; swi[wid] = bidx; }
    __syncthreads();
    if (wid == 0) {
        float b2 = (lane < NWARPS) ? swb[lane] : -1.0f;
        int   i2 = (lane < NWARPS) ? swi[lane] : 0x7fffffff;
        #pragma unroll
        for (int off = 4; off > 0; off >>= 1) {
            float ob = __shfl_down_sync(0xffffffffu, b2, off);
            int   oi = __shfl_down_sync(0xffffffffu, i2, off);
            if (ob > b2 || (ob == b2 && oi < i2)) { b2 = ob; i2 = oi; }
        }
        if (lane == 0) { s_maxiou = b2; s_midx = i2; }
    }
    __syncthreads();
    float maxiou = s_maxiou;
    int   midx   = s_midx;
    float posw   = (maxiou > 0.3f) ? 1.0f : 0.0f;

    // ---------------- Stage B: target gather + BCE ----------------
    float acc = 0.0f;
    if (posw != 0.0f) {
        float4 bb = __ldg((const float4*)gt_boxes + midx);
        // truncation toward zero matches astype(int32) for non-negative coords
        int x1 = min(max((int)bb.x, 0), W - 1);
        int y1 = min(max((int)bb.y, 0), H - 1);
        int x2 = max(x1 + 1, min((int)bb.z, W));
        int y2 = max(y1 + 1, min((int)bb.w, H));
        float cw = (float)(x2 - x1);
        float ch = (float)(y2 - y1);
        int cwi = x2 - x1;
        int chi = y2 - y1;

        const float* m  = gt_masks + (size_t)midx * H * W;
        const float* lg = mask_logits + (size_t)p * 2 * MASK_CELLS + MASK_CELLS;

        // fully unrolled so all loads issue up front (high MLP)
        float t00[4], t01[4], t10[4], t11[4], lgt[4], wyv[4], wxv[4];
        bool  act[4];
        #pragma unroll
        for (int it = 0; it < 4; ++it) {
            int cell = tid + it * NTHREADS;
            act[it] = (cell < MASK_CELLS);
            int c = act[it] ? cell : 0;
            int yj = c / MASK_SIZE;
            int xi = c - yj * MASK_SIZE;

            float sy = (yj + 0.5f) * ch * (1.0f / MASK_SIZE) - 0.5f;
            sy = fminf(fmaxf(sy, 0.0f), ch - 1.0f);
            float sx = (xi + 0.5f) * cw * (1.0f / MASK_SIZE) - 0.5f;
            sx = fminf(fmaxf(sx, 0.0f), cw - 1.0f);

            int y0 = (int)floorf(sy);
            int x0 = (int)floorf(sx);
            int yp = min(y0 + 1, chi - 1);
            int xp = min(x0 + 1, cwi - 1);
            wyv[it] = sy - (float)y0;
            wxv[it] = sx - (float)x0;

            int Y0 = y1 + y0, Y1 = y1 + yp;
            int X0 = x1 + x0, X1 = x1 + xp;

            t00[it] = __ldg(&m[(size_t)Y0 * W + X0]);
            t01[it] = __ldg(&m[(size_t)Y0 * W + X1]);
            t10[it] = __ldg(&m[(size_t)Y1 * W + X0]);
            t11[it] = __ldg(&m[(size_t)Y1 * W + X1]);
            lgt[it] = __ldg(&lg[c]);
        }
        #pragma unroll
        for (int it = 0; it < 4; ++it) {
            if (act[it]) {
                float wy = wyv[it], wx = wxv[it];
                float tgt = (1.0f - wy) * ((1.0f - wx) * t00[it] + wx * t01[it])
                          +          wy * ((1.0f - wx) * t10[it] + wx * t11[it]);
                float l = lgt[it];
                // softplus(l) - l*tgt == jnp.logaddexp(l, 0) - l*tgt
                acc += fmaxf(l, 0.0f) + log1pf(expf(-fabsf(l))) - l * tgt;
            }
        }
    }

    // block sum: warp shuffle, then cross-warp
    #pragma unroll
    for (int off = 16; off > 0; off >>= 1)
        acc += __shfl_down_sync(0xffffffffu, acc, off);
    if (lane == 0) sred[wid] = acc;
    __syncthreads();
    if (tid == 0) {
        float s = 0.0f;
        #pragma unroll
        for (int i = 0; i < NWARPS; ++i) s += sred[i];
        g_partial[p] = s;
        g_pos[p]     = posw;
        __threadfence();
        unsigned int prev = atomicAdd(&g_done, 1u);
        s_is_last = (prev == (unsigned int)(gridDim.x - 1)) ? 1 : 0;
    }
    __syncthreads();

    // ---------------- Stage C: last block finalizes ----------------
    if (s_is_last) {
        float s = 0.0f, c = 0.0f;
        for (int i = tid; i < P; i += NTHREADS) {
            s += g_partial[i];
            c += g_pos[i];
        }
        #pragma unroll
        for (int off = 16; off > 0; off >>= 1) {
            s += __shfl_down_sync(0xffffffffu, s, off);
            c += __shfl_down_sync(0xffffffffu, c, off);
        }
        if (lane == 0) { sred[wid] = s; sred2[wid] = c; }
        __syncthreads();
        if (tid == 0) {
            float ts = 0.0f, tc = 0.0f;
            #pragma unroll
            for (int i = 0; i < NWARPS; ++i) { ts += sred[i]; tc += sred2[i]; }
            float denom = fmaxf(tc, 1.0f) * (float)MASK_CELLS;
            out[0] = (tc > 0.0f) ? (ts / denom) : 0.0f;
            g_done = 0;   // reset for next graph replay
        }
    }
}

// ---------------------------------------------------------------------------
// Inputs (metadata order):
//  0: mask_logits  float32  P*2*28*28
//  1: proposals    float32  P*4
//  2: gt_boxes     float32  G*4
//  3: gt_masks     float32  G*H*W
//  4: gt_labels    int32    G        (unused by the reference math)
// Output: scalar float32
// ---------------------------------------------------------------------------
extern "C" void kernel_launch(void* const* d_in, const int* in_sizes, int n_in,
                              void* d_out, int out_size)
{
    const float* mask_logits = (const float*)d_in[0];
    const float* proposals   = (const float*)d_in[1];
    const float* gt_boxes    = (const float*)d_in[2];
    const float* gt_masks    = (const float*)d_in[3];

    int P = in_sizes[1] / 4;
    int G = in_sizes[2] / 4;
    int HW = in_sizes[3] / G;
    int H = 520;
    int W = HW / H;

    float* out = (float*)d_out;

    fused_maskrcnn_kernel<<<P, NTHREADS>>>(mask_logits, proposals, gt_boxes,
                                           gt_masks, out, P, G, H, W);
}

// round 5
// speedup vs baseline: 4.9035x; 1.0058x over previous
#include <cuda_runtime.h>
#include <cuda_bf16.h>
#include <math.h>

#define MASK_SIZE 28
#define MASK_CELLS (MASK_SIZE * MASK_SIZE)   // 784
#define MAX_P 1024
#define NTHREADS 256
#define NWARPS (NTHREADS / 32)

// Scratch (device globals — no allocation allowed)
__device__ float2 g_pp[MAX_P];          // (.x = partial bce sum, .y = pos flag)
__device__ unsigned int g_done = 0;

// ---------------------------------------------------------------------------
// Fused kernel: one block per proposal.
//  Entry: hoist independent logits loads + softplus (overlaps Stage A)
//  A: IoU row p over G gt boxes, shuffle argmax (first-max tiebreak)
//  B: bilinear target gather (16 front-batched taps) + l*tgt sum
//  C: last block finalizes deterministically
// ---------------------------------------------------------------------------
__global__ void __launch_bounds__(NTHREADS)
fused_maskrcnn_kernel(const float* __restrict__ mask_logits,
                      const float* __restrict__ proposals,
                      const float* __restrict__ gt_boxes,
                      const float* __restrict__ gt_masks,
                      float* __restrict__ out,
                      int P, int G, int H, int W)
{
    int p    = blockIdx.x;
    int tid  = threadIdx.x;
    int lane = tid & 31;
    int wid  = tid >> 5;

    __shared__ float swb[NWARPS];
    __shared__ int   swi[NWARPS];
    __shared__ float sred[NWARPS];
    __shared__ float sred2[NWARPS];
    __shared__ float s_maxiou;
    __shared__ int   s_midx;
    __shared__ int   s_is_last;

    // ---- hoisted: logits loads (independent of IoU result) ----
    const float* lg = mask_logits + (size_t)p * 2 * MASK_CELLS + MASK_CELLS;
    float lgt[4];
    bool  act[4];
    int   cellv[4];
    #pragma unroll
    for (int it = 0; it < 4; ++it) {
        int cell = tid + it * NTHREADS;
        act[it]  = (cell < MASK_CELLS);
        cellv[it] = act[it] ? cell : 0;
        lgt[it]  = __ldg(&lg[cellv[it]]);
    }

    // ---------------- Stage A: IoU row + argmax ----------------
    float4 a = __ldg((const float4*)proposals + p);
    float area_a = (a.z - a.x) * (a.w - a.y);

    float best = -1.0f;
    int   bidx = 0x7fffffff;
    for (int g = tid; g < G; g += NTHREADS) {
        float4 b = __ldg((const float4*)gt_boxes + g);
        float area_b = (b.z - b.x) * (b.w - b.y);
        float lx = fmaxf(a.x, b.x);
        float ly = fmaxf(a.y, b.y);
        float rx = fminf(a.z, b.z);
        float ry = fminf(a.w, b.w);
        float w = fmaxf(rx - lx, 0.0f);
        float h = fmaxf(ry - ly, 0.0f);
        float inter = w * h;
        float iou = inter / (area_a + area_b - inter);
        if (iou > best) { best = iou; bidx = g; }   // strict >: lowest g kept
    }
    #pragma unroll
    for (int off = 16; off > 0; off >>= 1) {
        float ob = __shfl_down_sync(0xffffffffu, best, off);
        int   oi = __shfl_down_sync(0xffffffffu, bidx, off);
        if (ob > best || (ob == best && oi < bidx)) { best = ob; bidx = oi; }
    }
    if (lane == 0) { swb[wid] = best; swi[wid] = bidx; }

    // softplus term while Stage A reduction finishes (no dependency on midx)
    float sp_sum = 0.0f;
    #pragma unroll
    for (int it = 0; it < 4; ++it) {
        float l = lgt[it];
        float sp = fmaxf(l, 0.0f) + log1pf(expf(-fabsf(l)));   // == logaddexp(l,0)
        if (act[it]) sp_sum += sp;
    }

    __syncthreads();
    if (wid == 0) {
        float b2 = (lane < NWARPS) ? swb[lane] : -1.0f;
        int   i2 = (lane < NWARPS) ? swi[lane] : 0x7fffffff;
        #pragma unroll
        for (int off = 4; off > 0; off >>= 1) {
            float ob = __shfl_down_sync(0xffffffffu, b2, off);
            int   oi = __shfl_down_sync(0xffffffffu, i2, off);
            if (ob > b2 || (ob == b2 && oi < i2)) { b2 = ob; i2 = oi; }
        }
        if (lane == 0) { s_maxiou = b2; s_midx = i2; }
    }
    __syncthreads();
    float posw = (s_maxiou > 0.3f) ? 1.0f : 0.0f;
    int   midx = s_midx;

    // ---------------- Stage B: target gather + l*tgt ----------------
    float acc = 0.0f;
    if (posw != 0.0f) {
        float4 bb = __ldg((const float4*)gt_boxes + midx);
        // truncation toward zero matches astype(int32) for non-negative coords
        int x1 = min(max((int)bb.x, 0), W - 1);
        int y1 = min(max((int)bb.y, 0), H - 1);
        int x2 = max(x1 + 1, min((int)bb.z, W));
        int y2 = max(y1 + 1, min((int)bb.w, H));
        float cw = (float)(x2 - x1);
        float ch = (float)(y2 - y1);
        int cwi = x2 - x1;
        int chi = y2 - y1;

        const float* m = gt_masks + (size_t)midx * H * W;

        float t00[4], t01[4], t10[4], t11[4], wyv[4], wxv[4];
        #pragma unroll
        for (int it = 0; it < 4; ++it) {
            int c  = cellv[it];
            int yj = c / MASK_SIZE;
            int xi = c - yj * MASK_SIZE;

            float sy = (yj + 0.5f) * ch * (1.0f / MASK_SIZE) - 0.5f;
            sy = fminf(fmaxf(sy, 0.0f), ch - 1.0f);
            float sx = (xi + 0.5f) * cw * (1.0f / MASK_SIZE) - 0.5f;
            sx = fminf(fmaxf(sx, 0.0f), cw - 1.0f);

            int y0 = (int)floorf(sy);
            int x0 = (int)floorf(sx);
            int yp = min(y0 + 1, chi - 1);
            int xp = min(x0 + 1, cwi - 1);
            wyv[it] = sy - (float)y0;
            wxv[it] = sx - (float)x0;

            int Y0 = y1 + y0, Y1 = y1 + yp;
            int X0 = x1 + x0, X1 = x1 + xp;

            t00[it] = __ldg(&m[(size_t)Y0 * W + X0]);
            t01[it] = __ldg(&m[(size_t)Y0 * W + X1]);
            t10[it] = __ldg(&m[(size_t)Y1 * W + X0]);
            t11[it] = __ldg(&m[(size_t)Y1 * W + X1]);
        }
        float lt_sum = 0.0f;
        #pragma unroll
        for (int it = 0; it < 4; ++it) {
            if (act[it]) {
                float wy = wyv[it], wx = wxv[it];
                float tgt = (1.0f - wy) * ((1.0f - wx) * t00[it] + wx * t01[it])
                          +          wy * ((1.0f - wx) * t10[it] + wx * t11[it]);
                lt_sum += lgt[it] * tgt;
            }
        }
        acc = sp_sum - lt_sum;   // Σ softplus(l) - Σ l*tgt  (exact regroup of ref sum)
    }

    // block sum: warp shuffle, then cross-warp
    #pragma unroll
    for (int off = 16; off > 0; off >>= 1)
        acc += __shfl_down_sync(0xffffffffu, acc, off);
    if (lane == 0) sred[wid] = acc;
    __syncthreads();
    if (tid == 0) {
        float s = 0.0f;
        #pragma unroll
        for (int i = 0; i < NWARPS; ++i) s += sred[i];
        g_pp[p] = make_float2(s, posw);
        __threadfence();
        unsigned int prev = atomicAdd(&g_done, 1u);
        s_is_last = (prev == (unsigned int)(gridDim.x - 1)) ? 1 : 0;
    }
    __syncthreads();

    // ---------------- Stage C: last block finalizes ----------------
    if (s_is_last) {
        float s = 0.0f, c = 0.0f;
        for (int i = tid; i < P; i += NTHREADS) {
            float2 v = g_pp[i];
            s += v.x;
            c += v.y;
        }
        #pragma unroll
        for (int off = 16; off > 0; off >>= 1) {
            s += __shfl_down_sync(0xffffffffu, s, off);
            c += __shfl_down_sync(0xffffffffu, c, off);
        }
        if (lane == 0) { sred[wid] = s; sred2[wid] = c; }
        __syncthreads();
        if (tid == 0) {
            float ts = 0.0f, tc = 0.0f;
            #pragma unroll
            for (int i = 0; i < NWARPS; ++i) { ts += sred[i]; tc += sred2[i]; }
            float denom = fmaxf(tc, 1.0f) * (float)MASK_CELLS;
            out[0] = (tc > 0.0f) ? (ts / denom) : 0.0f;
            g_done = 0;   // reset for next graph replay
        }
    }
}

// ---------------------------------------------------------------------------
// Inputs (metadata order):
//  0: mask_logits  float32  P*2*28*28
//  1: proposals    float32  P*4
//  2: gt_boxes     float32  G*4
//  3: gt_masks     float32  G*H*W
//  4: gt_labels    int32    G        (unused by the reference math)
// Output: scalar float32
// ---------------------------------------------------------------------------
extern "C" void kernel_launch(void* const* d_in, const int* in_sizes, int n_in,
                              void* d_out, int out_size)
{
    const float* mask_logits = (const float*)d_in[0];
    const float* proposals   = (const float*)d_in[1];
    const float* gt_boxes    = (const float*)d_in[2];
    const float* gt_masks    = (const float*)d_in[3];

    int P = in_sizes[1] / 4;
    int G = in_sizes[2] / 4;
    int HW = in_sizes[3] / G;
    int H = 520;
    int W = HW / H;

    float* out = (float*)d_out;

    fused_maskrcnn_kernel<<<P, NTHREADS>>>(mask_logits, proposals, gt_boxes,
                                           gt_masks, out, P, G, H, W);
}

// round 6
// speedup vs baseline: 5.0060x; 1.0209x over previous
#include <cuda_runtime.h>
#include <cuda_bf16.h>
#include <math.h>

#define MASK_SIZE 28
#define MASK_CELLS (MASK_SIZE * MASK_SIZE)   // 784
#define MAX_P 1024
#define NTHREADS 512
#define NWARPS (NTHREADS / 32)               // 16
#define NCELLS 2                              // cells per thread

// Scratch (device globals — no allocation allowed)
__device__ float2 g_pp[MAX_P];          // (.x = partial bce sum, .y = pos flag)
__device__ unsigned int g_done = 0;

// ---------------------------------------------------------------------------
// Fused kernel: one block (512 thr) per proposal.
//  Entry: hoist independent logits loads + softplus (overlaps Stage A)
//  A: IoU row p over G gt boxes, shuffle argmax (first-max tiebreak)
//  B: bilinear target gather (front-batched taps) + l*tgt sum
//  C: last block finalizes deterministically
// ---------------------------------------------------------------------------
__global__ void __launch_bounds__(NTHREADS)
fused_maskrcnn_kernel(const float* __restrict__ mask_logits,
                      const float* __restrict__ proposals,
                      const float* __restrict__ gt_boxes,
                      const float* __restrict__ gt_masks,
                      float* __restrict__ out,
                      int P, int G, int H, int W)
{
    int p    = blockIdx.x;
    int tid  = threadIdx.x;
    int lane = tid & 31;
    int wid  = tid >> 5;

    __shared__ float swb[NWARPS];
    __shared__ int   swi[NWARPS];
    __shared__ float sred[NWARPS];
    __shared__ float sred2[NWARPS];
    __shared__ float s_maxiou;
    __shared__ int   s_midx;
    __shared__ int   s_is_last;

    // ---- hoisted: logits loads (independent of IoU result) ----
    const float* lg = mask_logits + (size_t)p * 2 * MASK_CELLS + MASK_CELLS;
    float lgt[NCELLS];
    bool  act[NCELLS];
    int   cellv[NCELLS];
    #pragma unroll
    for (int it = 0; it < NCELLS; ++it) {
        int cell = tid + it * NTHREADS;
        act[it]  = (cell < MASK_CELLS);
        cellv[it] = act[it] ? cell : 0;
        lgt[it]  = __ldg(&lg[cellv[it]]);
    }

    // ---------------- Stage A: IoU row + argmax ----------------
    float4 a = __ldg((const float4*)proposals + p);
    float area_a = (a.z - a.x) * (a.w - a.y);

    float best = -1.0f;
    int   bidx = 0x7fffffff;
    for (int g = tid; g < G; g += NTHREADS) {
        float4 b = __ldg((const float4*)gt_boxes + g);
        float area_b = (b.z - b.x) * (b.w - b.y);
        float lx = fmaxf(a.x, b.x);
        float ly = fmaxf(a.y, b.y);
        float rx = fminf(a.z, b.z);
        float ry = fminf(a.w, b.w);
        float w = fmaxf(rx - lx, 0.0f);
        float h = fmaxf(ry - ly, 0.0f);
        float inter = w * h;
        float iou = inter / (area_a + area_b - inter);
        if (iou > best) { best = iou; bidx = g; }   // strict >: lowest g kept
    }
    #pragma unroll
    for (int off = 16; off > 0; off >>= 1) {
        float ob = __shfl_down_sync(0xffffffffu, best, off);
        int   oi = __shfl_down_sync(0xffffffffu, bidx, off);
        if (ob > best || (ob == best && oi < bidx)) { best = ob; bidx = oi; }
    }
    if (lane == 0) { swb[wid] = best; swi[wid] = bidx; }

    // softplus term while Stage A reduction finishes (no dependency on midx)
    float sp_sum = 0.0f;
    #pragma unroll
    for (int it = 0; it < NCELLS; ++it) {
        float l = lgt[it];
        float sp = fmaxf(l, 0.0f) + log1pf(expf(-fabsf(l)));   // == logaddexp(l,0)
        if (act[it]) sp_sum += sp;
    }

    __syncthreads();
    if (wid == 0) {
        float b2 = (lane < NWARPS) ? swb[lane] : -1.0f;
        int   i2 = (lane < NWARPS) ? swi[lane] : 0x7fffffff;
        #pragma unroll
        for (int off = 8; off > 0; off >>= 1) {
            float ob = __shfl_down_sync(0xffffffffu, b2, off);
            int   oi = __shfl_down_sync(0xffffffffu, i2, off);
            if (ob > b2 || (ob == b2 && oi < i2)) { b2 = ob; i2 = oi; }
        }
        if (lane == 0) { s_maxiou = b2; s_midx = i2; }
    }
    __syncthreads();
    float posw = (s_maxiou > 0.3f) ? 1.0f : 0.0f;
    int   midx = s_midx;

    // ---------------- Stage B: target gather + l*tgt ----------------
    float acc = 0.0f;
    if (posw != 0.0f) {
        float4 bb = __ldg((const float4*)gt_boxes + midx);
        // truncation toward zero matches astype(int32) for non-negative coords
        int x1 = min(max((int)bb.x, 0), W - 1);
        int y1 = min(max((int)bb.y, 0), H - 1);
        int x2 = max(x1 + 1, min((int)bb.z, W));
        int y2 = max(y1 + 1, min((int)bb.w, H));
        float cw = (float)(x2 - x1);
        float ch = (float)(y2 - y1);
        int cwi = x2 - x1;
        int chi = y2 - y1;

        const float* m = gt_masks + (size_t)midx * H * W;

        float t00[NCELLS], t01[NCELLS], t10[NCELLS], t11[NCELLS];
        float wyv[NCELLS], wxv[NCELLS];
        #pragma unroll
        for (int it = 0; it < NCELLS; ++it) {
            int c  = cellv[it];
            int yj = c / MASK_SIZE;
            int xi = c - yj * MASK_SIZE;

            float sy = (yj + 0.5f) * ch * (1.0f / MASK_SIZE) - 0.5f;
            sy = fminf(fmaxf(sy, 0.0f), ch - 1.0f);
            float sx = (xi + 0.5f) * cw * (1.0f / MASK_SIZE) - 0.5f;
            sx = fminf(fmaxf(sx, 0.0f), cw - 1.0f);

            int y0 = (int)floorf(sy);
            int x0 = (int)floorf(sx);
            int yp = min(y0 + 1, chi - 1);
            int xp = min(x0 + 1, cwi - 1);
            wyv[it] = sy - (float)y0;
            wxv[it] = sx - (float)x0;

            int Y0 = y1 + y0, Y1 = y1 + yp;
            int X0 = x1 + x0, X1 = x1 + xp;

            t00[it] = __ldg(&m[(size_t)Y0 * W + X0]);
            t01[it] = __ldg(&m[(size_t)Y0 * W + X1]);
            t10[it] = __ldg(&m[(size_t)Y1 * W + X0]);
            t11[it] = __ldg(&m[(size_t)Y1 * W + X1]);
        }
        float lt_sum = 0.0f;
        #pragma unroll
        for (int it = 0; it < NCELLS; ++it) {
            if (act[it]) {
                float wy = wyv[it], wx = wxv[it];
                float tgt = (1.0f - wy) * ((1.0f - wx) * t00[it] + wx * t01[it])
                          +          wy * ((1.0f - wx) * t10[it] + wx * t11[it]);
                lt_sum += lgt[it] * tgt;
            }
        }
        acc = sp_sum - lt_sum;   // Σ softplus(l) - Σ l*tgt  (exact regroup of ref sum)
    }

    // block sum: warp shuffle, then cross-warp
    #pragma unroll
    for (int off = 16; off > 0; off >>= 1)
        acc += __shfl_down_sync(0xffffffffu, acc, off);
    if (lane == 0) sred[wid] = acc;
    __syncthreads();
    if (tid == 0) {
        float s = 0.0f;
        #pragma unroll
        for (int i = 0; i < NWARPS; ++i) s += sred[i];
        g_pp[p] = make_float2(s, posw);
        __threadfence();
        unsigned int prev = atomicAdd(&g_done, 1u);
        s_is_last = (prev == (unsigned int)(gridDim.x - 1)) ? 1 : 0;
    }
    __syncthreads();

    // ---------------- Stage C: last block finalizes ----------------
    if (s_is_last) {
        float s = 0.0f, c = 0.0f;
        for (int i = tid; i < P; i += NTHREADS) {
            float2 v = g_pp[i];
            s += v.x;
            c += v.y;
        }
        #pragma unroll
        for (int off = 16; off > 0; off >>= 1) {
            s += __shfl_down_sync(0xffffffffu, s, off);
            c += __shfl_down_sync(0xffffffffu, c, off);
        }
        if (lane == 0) { sred[wid] = s; sred2[wid] = c; }
        __syncthreads();
        if (tid == 0) {
            float ts = 0.0f, tc = 0.0f;
            #pragma unroll
            for (int i = 0; i < NWARPS; ++i) { ts += sred[i]; tc += sred2[i]; }
            float denom = fmaxf(tc, 1.0f) * (float)MASK_CELLS;
            out[0] = (tc > 0.0f) ? (ts / denom) : 0.0f;
            g_done = 0;   // reset for next graph replay
        }
    }
}

// ---------------------------------------------------------------------------
// Inputs (metadata order):
//  0: mask_logits  float32  P*2*28*28
//  1: proposals    float32  P*4
//  2: gt_boxes     float32  G*4
//  3: gt_masks     float32  G*H*W
//  4: gt_labels    int32    G        (unused by the reference math)
// Output: scalar float32
// ---------------------------------------------------------------------------
extern "C" void kernel_launch(void* const* d_in, const int* in_sizes, int n_in,
                              void* d_out, int out_size)
{
    const float* mask_logits = (const float*)d_in[0];
    const float* proposals   = (const float*)d_in[1];
    const float* gt_boxes    = (const float*)d_in[2];
    const float* gt_masks    = (const float*)d_in[3];

    int P = in_sizes[1] / 4;
    int G = in_sizes[2] / 4;
    int HW = in_sizes[3] / G;
    int H = 520;
    int W = HW / H;

    float* out = (float*)d_out;

    fused_maskrcnn_kernel<<<P, NTHREADS>>>(mask_logits, proposals, gt_boxes,
                                           gt_masks, out, P, G, H, W);
}